// round 3
// baseline (speedup 1.0000x reference)
#include <cuda_runtime.h>

// Problem constants
#define Bdim 8
#define Tdim 64
#define Ndim 128
#define FINдim_unused 64
#define Ddim 64
#define LAGn 8
#define ROWS (Bdim*Tdim*Ndim)   // 65536

// Scratch (no cudaMalloc allowed): Q, K(pre-scaled by 1/8), V
__device__ float g_Q[ROWS*Ddim];
__device__ float g_K[ROWS*Ddim];
__device__ float g_V[ROWS*Ddim];

// ---------------------------------------------------------------------------
// Kernel 1: QKV projection. grid = (ROWS/64, 3). blockIdx.y: 0=Q,1=K,2=V.
// out = relu(X @ W + b)  (* 0.125 for K, folding in 1/sqrt(D))
// ---------------------------------------------------------------------------
__global__ __launch_bounds__(256) void qkv_kernel(
    const float* __restrict__ X,
    const float* __restrict__ Wq, const float* __restrict__ bq,
    const float* __restrict__ Wk, const float* __restrict__ bk,
    const float* __restrict__ Wv, const float* __restrict__ bv)
{
    __shared__ float XsT[64*64];   // [f][r]  (transposed X tile)
    __shared__ float Ws [64*64];   // [f][d]
    __shared__ float bs [64];

    const float* W; const float* bias; float* outp; float scale;
    if (blockIdx.y == 0)      { W = Wq; bias = bq; outp = g_Q; scale = 1.0f;   }
    else if (blockIdx.y == 1) { W = Wk; bias = bk; outp = g_K; scale = 0.125f; }
    else                      { W = Wv; bias = bv; outp = g_V; scale = 1.0f;   }

    const int r0  = blockIdx.x * 64;
    const int tid = threadIdx.x;

    // Load X tile (64 rows x 64 f), store transposed. 1024 float4s.
    {
        const float4* Xg = reinterpret_cast<const float4*>(X + (size_t)r0 * 64);
        const float4* Wg = reinterpret_cast<const float4*>(W);
        #pragma unroll
        for (int q = 0; q < 4; ++q) {
            int idx4 = tid + q * 256;           // 0..1023
            int r = idx4 >> 4;
            int f = (idx4 & 15) << 2;
            float4 v = Xg[idx4];
            XsT[(f+0)*64 + r] = v.x;
            XsT[(f+1)*64 + r] = v.y;
            XsT[(f+2)*64 + r] = v.z;
            XsT[(f+3)*64 + r] = v.w;
            // W: natural [f][d] layout, linear copy
            int wf = idx4 >> 4;
            int wd = (idx4 & 15) << 2;
            float4 wv4 = Wg[idx4];
            *reinterpret_cast<float4*>(&Ws[wf*64 + wd]) = wv4;
        }
        if (tid < 64) bs[tid] = bias[tid];
    }
    __syncthreads();

    const int tx = tid & 15;
    const int ty = tid >> 4;

    float acc[4][4] = {};
    #pragma unroll 16
    for (int k = 0; k < 64; ++k) {
        float4 a = *reinterpret_cast<const float4*>(&XsT[k*64 + (ty<<2)]);
        float4 b = *reinterpret_cast<const float4*>(&Ws [k*64 + (tx<<2)]);
        float av[4] = {a.x, a.y, a.z, a.w};
        float bv4[4] = {b.x, b.y, b.z, b.w};
        #pragma unroll
        for (int i = 0; i < 4; ++i)
            #pragma unroll
            for (int j = 0; j < 4; ++j)
                acc[i][j] = fmaf(av[i], bv4[j], acc[i][j]);
    }

    #pragma unroll
    for (int i = 0; i < 4; ++i) {
        int r = r0 + (ty<<2) + i;
        float4 o;
        o.x = fmaxf(acc[i][0] + bs[(tx<<2)+0], 0.0f) * scale;
        o.y = fmaxf(acc[i][1] + bs[(tx<<2)+1], 0.0f) * scale;
        o.z = fmaxf(acc[i][2] + bs[(tx<<2)+2], 0.0f) * scale;
        o.w = fmaxf(acc[i][3] + bs[(tx<<2)+3], 0.0f) * scale;
        *reinterpret_cast<float4*>(&outp[(size_t)r*64 + (tx<<2)]) = o;
    }
}

// ---------------------------------------------------------------------------
// Kernel 2: fused lag-attention + output projection.
// grid = B*T*2 (each CTA: one (b,t) and 64 of the 128 query heads).
// Flash-style streaming softmax over the LAG=8 key chunks of 128 keys each.
// ---------------------------------------------------------------------------
#define SMEM_ATTN ((64*64 + 64*128 + 128*64 + 128*64) * 4)   // 114688 B

__global__ __launch_bounds__(256, 2) void attn_kernel(
    const float* __restrict__ Wo, const float* __restrict__ bo,
    float* __restrict__ out)
{
    extern __shared__ float sm[];
    float* Qst = sm;                 // [64 k][64 r]   Q transposed
    float* KsT = Qst + 64*64;        // [64 k][128 m]  K chunk transposed (pre-scaled)
    float* Vs  = KsT + 64*128;       // [128 m][64 d]  V chunk
    float* Pt  = Vs  + 128*64;       // [128 m][64 r]  P transposed
    float* aggT = KsT;               // alias after loop: [64 d][64 r]
    float* Wos  = Pt;                // alias after loop: [128 c][64 d]

    const int gid  = blockIdx.x;
    const int half = gid & 1;
    const int bt   = gid >> 1;              // b*T + t
    const int t    = bt & (Tdim - 1);
    const int tid  = threadIdx.x;
    const int tx   = tid & 15;
    const int ty   = tid >> 4;

    // Load Q tile (rows half*64 .. +63), transposed into Qst.
    {
        const float4* Qg = reinterpret_cast<const float4*>(
            g_Q + (size_t)(bt * Ndim + half * 64) * Ddim);
        #pragma unroll
        for (int q = 0; q < 4; ++q) {
            int idx4 = tid + q * 256;        // 0..1023
            int r = idx4 >> 4;
            int f = (idx4 & 15) << 2;
            float4 v = Qg[idx4];
            Qst[(f+0)*64 + r] = v.x;
            Qst[(f+1)*64 + r] = v.y;
            Qst[(f+2)*64 + r] = v.z;
            Qst[(f+3)*64 + r] = v.w;
        }
    }

    float m_i[4], l_i[4], O[4][4];
    #pragma unroll
    for (int i = 0; i < 4; ++i) {
        m_i[i] = -1e30f; l_i[i] = 0.0f;
        #pragma unroll
        for (int j = 0; j < 4; ++j) O[i][j] = 0.0f;
    }

    const int nvalid = (t + 1 < LAGn) ? (t + 1) : LAGn;

    for (int l = 0; l < nvalid; ++l) {
        const int bt2 = bt - l;
        __syncthreads();   // Qst ready (l=0); prev GEMM2 done with Vs/Pt (l>0)

        // Load K chunk (transposed) and V chunk (linear). 2048 float4s each.
        {
            const float4* Kg = reinterpret_cast<const float4*>(g_K + (size_t)bt2 * Ndim * Ddim);
            const float4* Vg = reinterpret_cast<const float4*>(g_V + (size_t)bt2 * Ndim * Ddim);
            #pragma unroll
            for (int q = 0; q < 8; ++q) {
                int idx4 = tid + q * 256;            // 0..2047
                int mrow = idx4 >> 4;
                int f = (idx4 & 15) << 2;
                float4 kv = Kg[idx4];
                KsT[(f+0)*128 + mrow] = kv.x;
                KsT[(f+1)*128 + mrow] = kv.y;
                KsT[(f+2)*128 + mrow] = kv.z;
                KsT[(f+3)*128 + mrow] = kv.w;
                reinterpret_cast<float4*>(Vs)[idx4] = Vg[idx4];
            }
        }
        __syncthreads();

        // GEMM1: s[i][j] over cols {tx*4+j} and {64+tx*4+j}
        float s[4][8];
        #pragma unroll
        for (int i = 0; i < 4; ++i)
            #pragma unroll
            for (int j = 0; j < 8; ++j) s[i][j] = 0.0f;

        #pragma unroll 8
        for (int k = 0; k < 64; ++k) {
            float4 a  = *reinterpret_cast<const float4*>(&Qst[k*64  + (ty<<2)]);
            float4 b0 = *reinterpret_cast<const float4*>(&KsT[k*128 + (tx<<2)]);
            float4 b1 = *reinterpret_cast<const float4*>(&KsT[k*128 + 64 + (tx<<2)]);
            float av[4] = {a.x, a.y, a.z, a.w};
            float bv8[8] = {b0.x, b0.y, b0.z, b0.w, b1.x, b1.y, b1.z, b1.w};
            #pragma unroll
            for (int i = 0; i < 4; ++i)
                #pragma unroll
                for (int j = 0; j < 8; ++j)
                    s[i][j] = fmaf(av[i], bv8[j], s[i][j]);
        }

        // Online softmax update (per-row stats across the 16 tx lanes)
        #pragma unroll
        for (int i = 0; i < 4; ++i) {
            float cm = s[i][0];
            #pragma unroll
            for (int j = 1; j < 8; ++j) cm = fmaxf(cm, s[i][j]);
            cm = fmaxf(cm, __shfl_xor_sync(0xffffffffu, cm, 1));
            cm = fmaxf(cm, __shfl_xor_sync(0xffffffffu, cm, 2));
            cm = fmaxf(cm, __shfl_xor_sync(0xffffffffu, cm, 4));
            cm = fmaxf(cm, __shfl_xor_sync(0xffffffffu, cm, 8));
            float mnew = fmaxf(m_i[i], cm);
            float sc   = __expf(m_i[i] - mnew);
            float rs = 0.0f;
            #pragma unroll
            for (int j = 0; j < 8; ++j) {
                float p = __expf(s[i][j] - mnew);
                s[i][j] = p;
                rs += p;
            }
            rs += __shfl_xor_sync(0xffffffffu, rs, 1);
            rs += __shfl_xor_sync(0xffffffffu, rs, 2);
            rs += __shfl_xor_sync(0xffffffffu, rs, 4);
            rs += __shfl_xor_sync(0xffffffffu, rs, 8);
            l_i[i] = l_i[i] * sc + rs;
            #pragma unroll
            for (int j = 0; j < 4; ++j) O[i][j] *= sc;
            m_i[i] = mnew;
        }

        // Store P transposed: Pt[m][r]
        #pragma unroll
        for (int j = 0; j < 4; ++j) {
            *reinterpret_cast<float4*>(&Pt[((tx<<2)+j)*64 + (ty<<2)]) =
                make_float4(s[0][j], s[1][j], s[2][j], s[3][j]);
            *reinterpret_cast<float4*>(&Pt[(64+(tx<<2)+j)*64 + (ty<<2)]) =
                make_float4(s[0][4+j], s[1][4+j], s[2][4+j], s[3][4+j]);
        }
        __syncthreads();

        // GEMM2: O += P @ V   (O cols = tx*4 .. +3)
        #pragma unroll 8
        for (int m = 0; m < 128; ++m) {
            float4 a = *reinterpret_cast<const float4*>(&Pt[m*64 + (ty<<2)]);
            float4 b = *reinterpret_cast<const float4*>(&Vs[m*64 + (tx<<2)]);
            float av[4] = {a.x, a.y, a.z, a.w};
            float bv4[4] = {b.x, b.y, b.z, b.w};
            #pragma unroll
            for (int i = 0; i < 4; ++i)
                #pragma unroll
                for (int j = 0; j < 4; ++j)
                    O[i][j] = fmaf(av[i], bv4[j], O[i][j]);
        }
    }

    // Zero-padded lag chunks (t-l < 0): scores are exactly 0 for all 128 keys,
    // V is 0 -> they only add 128*exp(-m) each to the denominator.
    {
        const int ninv = LAGn - nvalid;
        if (ninv > 0) {
            #pragma unroll
            for (int i = 0; i < 4; ++i) {
                float mnew = fmaxf(m_i[i], 0.0f);
                float sc   = __expf(m_i[i] - mnew);
                l_i[i] = l_i[i] * sc + (float)ninv * 128.0f * __expf(-mnew);
                #pragma unroll
                for (int j = 0; j < 4; ++j) O[i][j] *= sc;
                m_i[i] = mnew;
            }
        }
    }

    // Normalize -> agg
    #pragma unroll
    for (int i = 0; i < 4; ++i) {
        float inv = 1.0f / l_i[i];
        #pragma unroll
        for (int j = 0; j < 4; ++j) O[i][j] *= inv;
    }

    __syncthreads();   // everyone done reading KsT/Vs/Pt

    // Stash agg transposed into KsT region; load Wo into Pt region.
    #pragma unroll
    for (int j = 0; j < 4; ++j) {
        *reinterpret_cast<float4*>(&aggT[((tx<<2)+j)*64 + (ty<<2)]) =
            make_float4(O[0][j], O[1][j], O[2][j], O[3][j]);
    }
    {
        const float4* Wg = reinterpret_cast<const float4*>(Wo);
        #pragma unroll
        for (int q = 0; q < 8; ++q) {
            int idx4 = tid + q * 256;   // 0..2047 (128*64/4)
            reinterpret_cast<float4*>(Wos)[idx4] = Wg[idx4];
        }
    }
    __syncthreads();

    // GEMM3: out = relu([Q | agg] @ Wo + bo)
    float acc[4][4] = {};
    #pragma unroll 8
    for (int c = 0; c < 64; ++c) {
        float4 a = *reinterpret_cast<const float4*>(&Qst[c*64 + (ty<<2)]);
        float4 b = *reinterpret_cast<const float4*>(&Wos[c*64 + (tx<<2)]);
        float av[4] = {a.x, a.y, a.z, a.w};
        float bv4[4] = {b.x, b.y, b.z, b.w};
        #pragma unroll
        for (int i = 0; i < 4; ++i)
            #pragma unroll
            for (int j = 0; j < 4; ++j)
                acc[i][j] = fmaf(av[i], bv4[j], acc[i][j]);
    }
    #pragma unroll 8
    for (int c = 0; c < 64; ++c) {
        float4 a = *reinterpret_cast<const float4*>(&aggT[c*64 + (ty<<2)]);
        float4 b = *reinterpret_cast<const float4*>(&Wos[(64+c)*64 + (tx<<2)]);
        float av[4] = {a.x, a.y, a.z, a.w};
        float bv4[4] = {b.x, b.y, b.z, b.w};
        #pragma unroll
        for (int i = 0; i < 4; ++i)
            #pragma unroll
            for (int j = 0; j < 4; ++j)
                acc[i][j] = fmaf(av[i], bv4[j], acc[i][j]);
    }

    float bo4[4];
    #pragma unroll
    for (int j = 0; j < 4; ++j) bo4[j] = bo[(tx<<2) + j];

    #pragma unroll
    for (int i = 0; i < 4; ++i) {
        int n = half * 64 + (ty<<2) + i;
        size_t row = (size_t)bt * Ndim + n;
        float4 o;
        o.x = fmaxf(acc[i][0] + bo4[0], 0.0f);
        o.y = fmaxf(acc[i][1] + bo4[1], 0.0f);
        o.z = fmaxf(acc[i][2] + bo4[2], 0.0f);
        o.w = fmaxf(acc[i][3] + bo4[3], 0.0f);
        *reinterpret_cast<float4*>(&out[row * Ddim + (tx<<2)]) = o;
    }
}

// ---------------------------------------------------------------------------
extern "C" void kernel_launch(void* const* d_in, const int* in_sizes, int n_in,
                              void* d_out, int out_size)
{
    const float* X  = (const float*)d_in[0];
    const float* Wq = (const float*)d_in[1];
    const float* bq = (const float*)d_in[2];
    const float* Wk = (const float*)d_in[3];
    const float* bk = (const float*)d_in[4];
    const float* Wv = (const float*)d_in[5];
    const float* bv = (const float*)d_in[6];
    const float* Wo = (const float*)d_in[7];
    const float* bo = (const float*)d_in[8];
    float* out = (float*)d_out;

    cudaFuncSetAttribute(attn_kernel,
                         cudaFuncAttributeMaxDynamicSharedMemorySize, SMEM_ATTN);

    qkv_kernel<<<dim3(ROWS/64, 3, 1), 256>>>(X, Wq, bq, Wk, bk, Wv, bv);
    attn_kernel<<<Bdim*Tdim*2, 256, SMEM_ATTN>>>(Wo, bo, out);
}

// round 4
// speedup vs baseline: 1.3920x; 1.3920x over previous
#include <cuda_runtime.h>

// Problem constants
#define Bdim 8
#define Tdim 64
#define Ndim 128
#define Ddim 64
#define LAGn 8
#define ROWS (Bdim*Tdim*Ndim)   // 65536

typedef unsigned long long u64;

// Scratch (no cudaMalloc allowed)
// g_Q: [bt][f=64][n=128]  (TRANSPOSED)
// g_K: [bt][f=64][m=128]  (TRANSPOSED, pre-scaled by 1/8)
// g_V: [bt][m=128][d=64]  (natural)
__device__ float g_Q[ROWS*Ddim];
__device__ float g_K[ROWS*Ddim];
__device__ float g_V[ROWS*Ddim];

// Packed fp32x2 helpers (sm_103a FFMA2 path — ptxas never auto-fuses these)
#define PKDUP(dst, f32v) asm("mov.b64 %0, {%1, %1};" : "=l"(dst) : "f"(f32v))
#define FMA2(acc, a, b)  asm("fma.rn.f32x2 %0, %1, %2, %0;" : "+l"(acc) : "l"(a), "l"(b))
#define MUL2(acc, a)     asm("mul.rn.f32x2 %0, %0, %1;" : "+l"(acc) : "l"(a))
#define UNPK(lo, hi, v)  asm("mov.b64 {%0, %1}, %2;" : "=f"(lo), "=f"(hi) : "l"(v))

// ---------------------------------------------------------------------------
// Kernel 1: QKV projection. grid = (ROWS/64, 3). blockIdx.y: 0=Q,1=K,2=V.
// out = relu(X @ W + b)  (* 0.125 for K). Q,K stored transposed per (b,t).
// ---------------------------------------------------------------------------
__global__ __launch_bounds__(256) void qkv_kernel(
    const float* __restrict__ X,
    const float* __restrict__ Wq, const float* __restrict__ bq,
    const float* __restrict__ Wk, const float* __restrict__ bk,
    const float* __restrict__ Wv, const float* __restrict__ bv)
{
    __shared__ float XsT[64*64];   // [f][r]  (transposed X tile)
    __shared__ float Ws [64*64];   // [f][d]
    __shared__ float bs [64];

    const float* W; const float* bias; float* outp; float scale;
    if (blockIdx.y == 0)      { W = Wq; bias = bq; outp = g_Q; scale = 1.0f;   }
    else if (blockIdx.y == 1) { W = Wk; bias = bk; outp = g_K; scale = 0.125f; }
    else                      { W = Wv; bias = bv; outp = g_V; scale = 1.0f;   }

    const int r0  = blockIdx.x * 64;
    const int tid = threadIdx.x;

    {
        const float4* Xg = reinterpret_cast<const float4*>(X + (size_t)r0 * 64);
        const float4* Wg = reinterpret_cast<const float4*>(W);
        #pragma unroll
        for (int q = 0; q < 4; ++q) {
            int idx4 = tid + q * 256;           // 0..1023
            int r = idx4 >> 4;
            int f = (idx4 & 15) << 2;
            float4 v = Xg[idx4];
            XsT[(f+0)*64 + r] = v.x;
            XsT[(f+1)*64 + r] = v.y;
            XsT[(f+2)*64 + r] = v.z;
            XsT[(f+3)*64 + r] = v.w;
            int wf = idx4 >> 4;
            int wd = (idx4 & 15) << 2;
            *reinterpret_cast<float4*>(&Ws[wf*64 + wd]) = Wg[idx4];
        }
        if (tid < 64) bs[tid] = bias[tid];
    }
    __syncthreads();

    const int tx = tid & 15;
    const int ty = tid >> 4;

    u64 acc[4][2] = {};
    #pragma unroll 8
    for (int k = 0; k < 64; ++k) {
        float4 a = *reinterpret_cast<const float4*>(&XsT[k*64 + (ty<<2)]);
        ulonglong2 b = *reinterpret_cast<const ulonglong2*>(&Ws[k*64 + (tx<<2)]);
        float av[4] = {a.x, a.y, a.z, a.w};
        #pragma unroll
        for (int i = 0; i < 4; ++i) {
            u64 ad; PKDUP(ad, av[i]);
            FMA2(acc[i][0], ad, b.x);
            FMA2(acc[i][1], ad, b.y);
        }
    }

    float o[4][4];
    #pragma unroll
    for (int i = 0; i < 4; ++i) {
        UNPK(o[i][0], o[i][1], acc[i][0]);
        UNPK(o[i][2], o[i][3], acc[i][1]);
        #pragma unroll
        for (int j = 0; j < 4; ++j)
            o[i][j] = fmaxf(o[i][j] + bs[(tx<<2)+j], 0.0f) * scale;
    }

    if (blockIdx.y == 2) {
        // V natural: [r][d]
        #pragma unroll
        for (int i = 0; i < 4; ++i) {
            int r = r0 + (ty<<2) + i;
            *reinterpret_cast<float4*>(&outp[(size_t)r*64 + (tx<<2)]) =
                make_float4(o[i][0], o[i][1], o[i][2], o[i][3]);
        }
    } else {
        // Q/K transposed: [bt][d][n], float4 along n (i covers 4 consecutive n)
        const int bt = r0 >> 7;
        const int nb = (r0 & 127) + (ty<<2);
        #pragma unroll
        for (int j = 0; j < 4; ++j) {
            int d = (tx<<2) + j;
            *reinterpret_cast<float4*>(&outp[(size_t)bt*8192 + d*128 + nb]) =
                make_float4(o[0][j], o[1][j], o[2][j], o[3][j]);
        }
    }
}

// ---------------------------------------------------------------------------
// Kernel 2: fused lag-attention + output projection.
// grid = B*T*2 (each CTA: one (b,t) and 64 of the 128 query heads).
// ---------------------------------------------------------------------------
#define SMEM_ATTN ((64*64 + 64*128 + 128*64 + 64*128) * 4)   // 114688 B

__global__ __launch_bounds__(256, 2) void attn_kernel(
    const float* __restrict__ Wo, const float* __restrict__ bo,
    float* __restrict__ out)
{
    extern __shared__ float sm[];
    float* Qst = sm;                 // [64 f][64 r]   Q (already transposed in gmem)
    float* KsT = Qst + 64*64;        // [64 f][128 m]  K chunk (already transposed)
    float* Vs  = KsT + 64*128;       // [128 m][64 d]  V chunk (natural)
    float* Ps  = Vs  + 128*64;       // [64 r][128 m]  P natural
    float* aggN = KsT;               // alias after loop: [64 r][64 d]
    float* Wos  = Ps;                // alias after loop: [128 c][64 d]

    const int gid  = blockIdx.x;
    const int half = gid & 1;
    const int bt   = gid >> 1;
    const int t    = bt & (Tdim - 1);
    const int tid  = threadIdx.x;
    const int tx   = tid & 15;
    const int ty   = tid >> 4;

    // Load Q tile: rows f=0..63, cols n = half*64..+63. Linear, conflict-free.
    {
        const float4* Qg = reinterpret_cast<const float4*>(g_Q + (size_t)bt*8192) + half*16;
        #pragma unroll
        for (int q = 0; q < 4; ++q) {
            int idx4 = tid + q * 256;        // 0..1023
            int f = idx4 >> 4;
            int c = idx4 & 15;
            reinterpret_cast<float4*>(Qst)[idx4] = Qg[f*32 + c];
        }
    }

    float m_i[4], l_i[4];
    u64 Op[4][2];
    #pragma unroll
    for (int i = 0; i < 4; ++i) {
        m_i[i] = -1e30f; l_i[i] = 0.0f;
        Op[i][0] = 0ull; Op[i][1] = 0ull;
    }

    const int nvalid = (t + 1 < LAGn) ? (t + 1) : LAGn;

    for (int l = 0; l < nvalid; ++l) {
        const int bt2 = bt - l;
        __syncthreads();   // Qst ready (l=0); prev GEMM2 done with Vs/Ps (l>0)

        // K chunk + V chunk: straight 32KB copies, conflict-free.
        {
            const float4* Kg = reinterpret_cast<const float4*>(g_K + (size_t)bt2 * 8192);
            const float4* Vg = reinterpret_cast<const float4*>(g_V + (size_t)bt2 * 8192);
            #pragma unroll
            for (int q = 0; q < 8; ++q) {
                int idx4 = tid + q * 256;            // 0..2047
                reinterpret_cast<float4*>(KsT)[idx4] = Kg[idx4];
                reinterpret_cast<float4*>(Vs )[idx4] = Vg[idx4];
            }
        }
        __syncthreads();

        // GEMM1 (packed f32x2): S = Q·K^T, cols tx*4..+3 and 64+tx*4..+3
        u64 sa[4][4];
        #pragma unroll
        for (int i = 0; i < 4; ++i)
            #pragma unroll
            for (int p = 0; p < 4; ++p) sa[i][p] = 0ull;

        #pragma unroll 8
        for (int k = 0; k < 64; ++k) {
            float4 a = *reinterpret_cast<const float4*>(&Qst[k*64 + (ty<<2)]);
            ulonglong2 b0 = *reinterpret_cast<const ulonglong2*>(&KsT[k*128 + (tx<<2)]);
            ulonglong2 b1 = *reinterpret_cast<const ulonglong2*>(&KsT[k*128 + 64 + (tx<<2)]);
            float av[4] = {a.x, a.y, a.z, a.w};
            #pragma unroll
            for (int i = 0; i < 4; ++i) {
                u64 ad; PKDUP(ad, av[i]);
                FMA2(sa[i][0], ad, b0.x);
                FMA2(sa[i][1], ad, b0.y);
                FMA2(sa[i][2], ad, b1.x);
                FMA2(sa[i][3], ad, b1.y);
            }
        }

        // Online softmax update
        float s[4][8];
        #pragma unroll
        for (int i = 0; i < 4; ++i) {
            UNPK(s[i][0], s[i][1], sa[i][0]);
            UNPK(s[i][2], s[i][3], sa[i][1]);
            UNPK(s[i][4], s[i][5], sa[i][2]);
            UNPK(s[i][6], s[i][7], sa[i][3]);
        }

        #pragma unroll
        for (int i = 0; i < 4; ++i) {
            float cm = s[i][0];
            #pragma unroll
            for (int j = 1; j < 8; ++j) cm = fmaxf(cm, s[i][j]);
            cm = fmaxf(cm, __shfl_xor_sync(0xffffffffu, cm, 1));
            cm = fmaxf(cm, __shfl_xor_sync(0xffffffffu, cm, 2));
            cm = fmaxf(cm, __shfl_xor_sync(0xffffffffu, cm, 4));
            cm = fmaxf(cm, __shfl_xor_sync(0xffffffffu, cm, 8));
            float mnew = fmaxf(m_i[i], cm);
            float sc   = __expf(m_i[i] - mnew);
            float rs = 0.0f;
            #pragma unroll
            for (int j = 0; j < 8; ++j) {
                float p = __expf(s[i][j] - mnew);
                s[i][j] = p;
                rs += p;
            }
            rs += __shfl_xor_sync(0xffffffffu, rs, 1);
            rs += __shfl_xor_sync(0xffffffffu, rs, 2);
            rs += __shfl_xor_sync(0xffffffffu, rs, 4);
            rs += __shfl_xor_sync(0xffffffffu, rs, 8);
            l_i[i] = l_i[i] * sc + rs;
            u64 scd; PKDUP(scd, sc);
            MUL2(Op[i][0], scd);
            MUL2(Op[i][1], scd);
            m_i[i] = mnew;
        }

        // Store P natural: [r][m]. Conflict-free STS.128.
        #pragma unroll
        for (int i = 0; i < 4; ++i) {
            int row = (ty<<2) + i;
            *reinterpret_cast<float4*>(&Ps[row*128 + (tx<<2)]) =
                make_float4(s[i][0], s[i][1], s[i][2], s[i][3]);
            *reinterpret_cast<float4*>(&Ps[row*128 + 64 + (tx<<2)]) =
                make_float4(s[i][4], s[i][5], s[i][6], s[i][7]);
        }
        __syncthreads();

        // GEMM2 (packed): O += P @ V.  P via broadcast float4 along m.
        #pragma unroll 2
        for (int m0 = 0; m0 < 128; m0 += 4) {
            float pv[4][4];
            #pragma unroll
            for (int i = 0; i < 4; ++i) {
                float4 pr = *reinterpret_cast<const float4*>(&Ps[((ty<<2)+i)*128 + m0]);
                pv[i][0] = pr.x; pv[i][1] = pr.y; pv[i][2] = pr.z; pv[i][3] = pr.w;
            }
            #pragma unroll
            for (int mm = 0; mm < 4; ++mm) {
                ulonglong2 vb = *reinterpret_cast<const ulonglong2*>(&Vs[(m0+mm)*64 + (tx<<2)]);
                #pragma unroll
                for (int i = 0; i < 4; ++i) {
                    u64 pd; PKDUP(pd, pv[i][mm]);
                    FMA2(Op[i][0], pd, vb.x);
                    FMA2(Op[i][1], pd, vb.y);
                }
            }
        }
    }

    // Zero-padded lags contribute 128*exp(-m) each to denominator only.
    // Fold rescale + normalization into one factor per row.
    float fac[4];
    {
        const int ninv = LAGn - nvalid;
        #pragma unroll
        for (int i = 0; i < 4; ++i) {
            float sc = 1.0f, lf = l_i[i];
            if (ninv > 0) {
                float mnew = fmaxf(m_i[i], 0.0f);
                sc = __expf(m_i[i] - mnew);
                lf = lf * sc + (float)ninv * 128.0f * __expf(-mnew);
            }
            fac[i] = sc / lf;
        }
    }

    __syncthreads();   // everyone done with KsT/Vs/Ps

    // agg natural [r][d] into KsT region; Wo into Ps region.
    #pragma unroll
    for (int i = 0; i < 4; ++i) {
        u64 fd; PKDUP(fd, fac[i]);
        MUL2(Op[i][0], fd);
        MUL2(Op[i][1], fd);
        float a0,a1,a2,a3;
        UNPK(a0, a1, Op[i][0]);
        UNPK(a2, a3, Op[i][1]);
        *reinterpret_cast<float4*>(&aggN[((ty<<2)+i)*64 + (tx<<2)]) =
            make_float4(a0, a1, a2, a3);
    }
    {
        const float4* Wg = reinterpret_cast<const float4*>(Wo);
        #pragma unroll
        for (int q = 0; q < 8; ++q) {
            int idx4 = tid + q * 256;   // 0..2047
            reinterpret_cast<float4*>(Wos)[idx4] = Wg[idx4];
        }
    }
    __syncthreads();

    // GEMM3: out = relu([Q | agg] @ Wo + bo)
    u64 ec[4][2] = {};
    #pragma unroll 8
    for (int c = 0; c < 64; ++c) {
        float4 a = *reinterpret_cast<const float4*>(&Qst[c*64 + (ty<<2)]);
        ulonglong2 wb = *reinterpret_cast<const ulonglong2*>(&Wos[c*64 + (tx<<2)]);
        float av[4] = {a.x, a.y, a.z, a.w};
        #pragma unroll
        for (int i = 0; i < 4; ++i) {
            u64 ad; PKDUP(ad, av[i]);
            FMA2(ec[i][0], ad, wb.x);
            FMA2(ec[i][1], ad, wb.y);
        }
    }
    #pragma unroll 2
    for (int c0 = 0; c0 < 64; c0 += 4) {
        float av[4][4];
        #pragma unroll
        for (int i = 0; i < 4; ++i) {
            float4 ar = *reinterpret_cast<const float4*>(&aggN[((ty<<2)+i)*64 + c0]);
            av[i][0] = ar.x; av[i][1] = ar.y; av[i][2] = ar.z; av[i][3] = ar.w;
        }
        #pragma unroll
        for (int cc = 0; cc < 4; ++cc) {
            ulonglong2 wb = *reinterpret_cast<const ulonglong2*>(&Wos[(64+c0+cc)*64 + (tx<<2)]);
            #pragma unroll
            for (int i = 0; i < 4; ++i) {
                u64 ad; PKDUP(ad, av[i][cc]);
                FMA2(ec[i][0], ad, wb.x);
                FMA2(ec[i][1], ad, wb.y);
            }
        }
    }

    float bo4[4];
    #pragma unroll
    for (int j = 0; j < 4; ++j) bo4[j] = bo[(tx<<2) + j];

    #pragma unroll
    for (int i = 0; i < 4; ++i) {
        float e0,e1,e2,e3;
        UNPK(e0, e1, ec[i][0]);
        UNPK(e2, e3, ec[i][1]);
        int n = half * 64 + (ty<<2) + i;
        size_t row = (size_t)bt * Ndim + n;
        float4 o;
        o.x = fmaxf(e0 + bo4[0], 0.0f);
        o.y = fmaxf(e1 + bo4[1], 0.0f);
        o.z = fmaxf(e2 + bo4[2], 0.0f);
        o.w = fmaxf(e3 + bo4[3], 0.0f);
        *reinterpret_cast<float4*>(&out[row * Ddim + (tx<<2)]) = o;
    }
}

// ---------------------------------------------------------------------------
extern "C" void kernel_launch(void* const* d_in, const int* in_sizes, int n_in,
                              void* d_out, int out_size)
{
    const float* X  = (const float*)d_in[0];
    const float* Wq = (const float*)d_in[1];
    const float* bq = (const float*)d_in[2];
    const float* Wk = (const float*)d_in[3];
    const float* bk = (const float*)d_in[4];
    const float* Wv = (const float*)d_in[5];
    const float* bv = (const float*)d_in[6];
    const float* Wo = (const float*)d_in[7];
    const float* bo = (const float*)d_in[8];
    float* out = (float*)d_out;

    cudaFuncSetAttribute(attn_kernel,
                         cudaFuncAttributeMaxDynamicSharedMemorySize, SMEM_ATTN);

    qkv_kernel<<<dim3(ROWS/64, 3, 1), 256>>>(X, Wq, bq, Wk, bk, Wv, bv);
    attn_kernel<<<Bdim*Tdim*2, 256, SMEM_ATTN>>>(Wo, bo, out);
}

// round 7
// speedup vs baseline: 1.5126x; 1.0867x over previous
#include <cuda_runtime.h>

// Problem constants
#define Bdim 8
#define Tdim 64
#define Ndim 128
#define Ddim 64
#define LAGn 8
#define ROWS (Bdim*Tdim*Ndim)   // 65536

typedef unsigned long long u64;

// Scratch (no cudaMalloc allowed)
// g_Q: [bt][f=64][n=128]  (TRANSPOSED)
// g_K: [bt][f=64][m=128]  (TRANSPOSED, pre-scaled by 1/8)
// g_V: [bt][m=128][d=64]  (natural)
__device__ float g_Q[ROWS*Ddim];
__device__ float g_K[ROWS*Ddim];
__device__ float g_V[ROWS*Ddim];

// Packed fp32x2 helpers (sm_103a FFMA2 path — ptxas never auto-fuses these)
#define PKDUP(dst, f32v) asm("mov.b64 %0, {%1, %1};" : "=l"(dst) : "f"(f32v))
#define FMA2(acc, a, b)  asm("fma.rn.f32x2 %0, %1, %2, %0;" : "+l"(acc) : "l"(a), "l"(b))
#define UNPK(lo, hi, v)  asm("mov.b64 {%0, %1}, %2;" : "=f"(lo), "=f"(hi) : "l"(v))

// ---------------------------------------------------------------------------
// Kernel 1: QKV projection. grid = (ROWS/64, 3). blockIdx.y: 0=Q,1=K,2=V.
// out = relu(X @ W + b)  (* 0.125 for K). Q,K stored transposed per (b,t).
// ---------------------------------------------------------------------------
__global__ __launch_bounds__(256) void qkv_kernel(
    const float* __restrict__ X,
    const float* __restrict__ Wq, const float* __restrict__ bq,
    const float* __restrict__ Wk, const float* __restrict__ bk,
    const float* __restrict__ Wv, const float* __restrict__ bv)
{
    __shared__ float XsT[64*64];   // [f][r]  (transposed X tile)
    __shared__ float Ws [64*64];   // [f][d]
    __shared__ float bs [64];

    const float* W; const float* bias; float* outp; float scale;
    if (blockIdx.y == 0)      { W = Wq; bias = bq; outp = g_Q; scale = 1.0f;   }
    else if (blockIdx.y == 1) { W = Wk; bias = bk; outp = g_K; scale = 0.125f; }
    else                      { W = Wv; bias = bv; outp = g_V; scale = 1.0f;   }

    const int r0  = blockIdx.x * 64;
    const int tid = threadIdx.x;

    {
        const float4* Xg = reinterpret_cast<const float4*>(X + (size_t)r0 * 64);
        const float4* Wg = reinterpret_cast<const float4*>(W);
        #pragma unroll
        for (int q = 0; q < 4; ++q) {
            int idx4 = tid + q * 256;           // 0..1023
            int r = idx4 >> 4;
            int f = (idx4 & 15) << 2;
            float4 v = Xg[idx4];
            XsT[(f+0)*64 + r] = v.x;
            XsT[(f+1)*64 + r] = v.y;
            XsT[(f+2)*64 + r] = v.z;
            XsT[(f+3)*64 + r] = v.w;
            *reinterpret_cast<float4*>(&Ws[(idx4 >> 4)*64 + ((idx4 & 15) << 2)]) = Wg[idx4];
        }
        if (tid < 64) bs[tid] = bias[tid];
    }
    __syncthreads();

    const int tx = tid & 15;
    const int ty = tid >> 4;

    u64 acc[4][2] = {};
    #pragma unroll 8
    for (int k = 0; k < 64; ++k) {
        float4 a = *reinterpret_cast<const float4*>(&XsT[k*64 + (ty<<2)]);
        ulonglong2 b = *reinterpret_cast<const ulonglong2*>(&Ws[k*64 + (tx<<2)]);
        float av[4] = {a.x, a.y, a.z, a.w};
        #pragma unroll
        for (int i = 0; i < 4; ++i) {
            u64 ad; PKDUP(ad, av[i]);
            FMA2(acc[i][0], ad, b.x);
            FMA2(acc[i][1], ad, b.y);
        }
    }

    float o[4][4];
    #pragma unroll
    for (int i = 0; i < 4; ++i) {
        UNPK(o[i][0], o[i][1], acc[i][0]);
        UNPK(o[i][2], o[i][3], acc[i][1]);
        #pragma unroll
        for (int j = 0; j < 4; ++j)
            o[i][j] = fmaxf(o[i][j] + bs[(tx<<2)+j], 0.0f) * scale;
    }

    if (blockIdx.y == 2) {
        // V natural: [r][d]
        #pragma unroll
        for (int i = 0; i < 4; ++i) {
            int r = r0 + (ty<<2) + i;
            *reinterpret_cast<float4*>(&outp[(size_t)r*64 + (tx<<2)]) =
                make_float4(o[i][0], o[i][1], o[i][2], o[i][3]);
        }
    } else {
        // Q/K transposed: [bt][d][n], float4 along n
        const int bt = r0 >> 7;
        const int nb = (r0 & 127) + (ty<<2);
        #pragma unroll
        for (int j = 0; j < 4; ++j) {
            int d = (tx<<2) + j;
            *reinterpret_cast<float4*>(&outp[(size_t)bt*8192 + d*128 + nb]) =
                make_float4(o[0][j], o[1][j], o[2][j], o[3][j]);
        }
    }
}

// ---------------------------------------------------------------------------
// Kernel 2: fused lag-attention + output projection.
// grid = B*T*2 (each CTA: one (b,t), 64 of the 128 query heads), 128 threads.
// Thread tile: GEMM1 8 rows x 8 cols (cols tx*4 & 64+tx*4); GEMM2 8 rows x 4 d.
// P stored in a paired-row interleave so a GEMM2 warp A-load hits ONE 128B line:
//   slot = (i*4 + w), slot stride 256 floats; float index within slot:
//     (m>>2)*8 + p*4 + (m&3)   [p distinguishes the two rows sharing the slot]
// No softmax max-tracking (scores bounded, post-ReLU operands): denominator
// accumulated per-thread, reduced once at the end.
// ---------------------------------------------------------------------------
#define SM_Q 0
#define SM_K 4096
#define SM_V 12288
#define SM_P 20480
#define SMEM_ATTN ((20480 + 8192)*4)   // 112 KB -> 2 CTAs/SM

__global__ __launch_bounds__(128, 2) void attn_kernel(
    const float* __restrict__ Wo, const float* __restrict__ bo,
    float* __restrict__ out)
{
    extern __shared__ float sm[];
    float* Qst = sm + SM_Q;     // [64 f][64 r]
    float* KsT = sm + SM_K;     // [64 f][128 m]
    float* Vs  = sm + SM_V;     // [128 m][64 d]
    float* Pp  = sm + SM_P;     // paired layout, 32 slots x 256 floats = 32 KB
    float* aggN = sm + SM_P;    // alias after loop: [64 r][64 d]
    float* Wos  = sm + SM_K;    // alias after loop: [128 c][64 d]

    const int gid  = blockIdx.x;
    const int half = gid & 1;
    const int bt   = gid >> 1;
    const int t    = bt & (Tdim - 1);
    const int tid  = threadIdx.x;
    const int tx   = tid & 15;
    const int ty   = tid >> 4;          // 0..7, 8 rows each
    const int w    = ty >> 1;
    const int p    = ty & 1;
    const int rbase = ty << 3;          // first of this thread's 8 rows

    // Load Q tile (cols half*64..+63 of transposed g_Q) + first K/V chunk.
    {
        const float4* Qg = reinterpret_cast<const float4*>(g_Q + (size_t)bt*8192) + half*16;
        const float4* Kg = reinterpret_cast<const float4*>(g_K + (size_t)bt*8192);
        const float4* Vg = reinterpret_cast<const float4*>(g_V + (size_t)bt*8192);
        #pragma unroll
        for (int q = 0; q < 8; ++q) {
            int idx4 = tid + q * 128;        // 0..1023
            reinterpret_cast<float4*>(Qst)[idx4] = Qg[(idx4 >> 4)*32 + (idx4 & 15)];
        }
        #pragma unroll
        for (int q = 0; q < 16; ++q) {
            int idx4 = tid + q * 128;        // 0..2047
            reinterpret_cast<float4*>(KsT)[idx4] = Kg[idx4];
            reinterpret_cast<float4*>(Vs )[idx4] = Vg[idx4];
        }
    }

    float dloc[8];
    u64 Op[8][2];
    #pragma unroll
    for (int i = 0; i < 8; ++i) { dloc[i] = 0.0f; Op[i][0] = 0ull; Op[i][1] = 0ull; }

    const int nvalid = (t + 1 < LAGn) ? (t + 1) : LAGn;

    for (int l = 0; l < nvalid; ++l) {
        if (l > 0) {
            __syncthreads();   // prev GEMM2 done with Vs/Pp
            const float4* Kg = reinterpret_cast<const float4*>(g_K + (size_t)(bt - l) * 8192);
            const float4* Vg = reinterpret_cast<const float4*>(g_V + (size_t)(bt - l) * 8192);
            #pragma unroll
            for (int q = 0; q < 16; ++q) {
                int idx4 = tid + q * 128;
                reinterpret_cast<float4*>(KsT)[idx4] = Kg[idx4];
                reinterpret_cast<float4*>(Vs )[idx4] = Vg[idx4];
            }
        }
        __syncthreads();

        // ---- GEMM1: S = Q·K^T, 8 rows x (cols tx*4..+3, 64+tx*4..+3) ----
        u64 sa[8][4];
        #pragma unroll
        for (int i = 0; i < 8; ++i)
            #pragma unroll
            for (int j = 0; j < 4; ++j) sa[i][j] = 0ull;

        #pragma unroll 4
        for (int k = 0; k < 64; ++k) {
            float4 a0 = *reinterpret_cast<const float4*>(&Qst[k*64 + rbase]);
            float4 a1 = *reinterpret_cast<const float4*>(&Qst[k*64 + rbase + 4]);
            ulonglong2 b0 = *reinterpret_cast<const ulonglong2*>(&KsT[k*128 + (tx<<2)]);
            ulonglong2 b1 = *reinterpret_cast<const ulonglong2*>(&KsT[k*128 + 64 + (tx<<2)]);
            float av[8] = {a0.x, a0.y, a0.z, a0.w, a1.x, a1.y, a1.z, a1.w};
            #pragma unroll
            for (int i = 0; i < 8; ++i) {
                u64 ad; PKDUP(ad, av[i]);
                FMA2(sa[i][0], ad, b0.x);
                FMA2(sa[i][1], ad, b0.y);
                FMA2(sa[i][2], ad, b1.x);
                FMA2(sa[i][3], ad, b1.y);
            }
        }

        // ---- exp + denominator partials + paired-layout P store ----
        #pragma unroll
        for (int i = 0; i < 8; ++i) {
            float e[8];
            UNPK(e[0], e[1], sa[i][0]);
            UNPK(e[2], e[3], sa[i][1]);
            UNPK(e[4], e[5], sa[i][2]);
            UNPK(e[6], e[7], sa[i][3]);
            float rs = 0.0f;
            #pragma unroll
            for (int j = 0; j < 8; ++j) { e[j] = __expf(e[j]); rs += e[j]; }
            dloc[i] += rs;
            float* base = &Pp[(((i<<2) + w) << 8) + (p<<2)];
            *reinterpret_cast<float4*>(base + (tx<<3)) =
                make_float4(e[0], e[1], e[2], e[3]);
            *reinterpret_cast<float4*>(base + ((16 + tx)<<3)) =
                make_float4(e[4], e[5], e[6], e[7]);
        }
        __syncthreads();

        // ---- GEMM2: O += P @ V, 8 rows x 4 d-cols (d = tx*4..+3) ----
        #pragma unroll 2
        for (int m0 = 0; m0 < 128; m0 += 4) {
            float ar[8][4];
            #pragma unroll
            for (int i = 0; i < 8; ++i) {
                float4 v = *reinterpret_cast<const float4*>(
                    &Pp[(((i<<2) + w) << 8) + ((m0 >> 2)<<3) + (p<<2)]);
                ar[i][0] = v.x; ar[i][1] = v.y; ar[i][2] = v.z; ar[i][3] = v.w;
            }
            #pragma unroll
            for (int mm = 0; mm < 4; ++mm) {
                ulonglong2 vb = *reinterpret_cast<const ulonglong2*>(&Vs[(m0+mm)*64 + (tx<<2)]);
                #pragma unroll
                for (int i = 0; i < 8; ++i) {
                    u64 pd; PKDUP(pd, ar[i][mm]);
                    FMA2(Op[i][0], pd, vb.x);
                    FMA2(Op[i][1], pd, vb.y);
                }
            }
        }
    }

    // ---- finalize denominators (reduce over the 16 tx lanes, once) ----
    const float padadd = (float)(LAGn - nvalid) * 128.0f;
    float inv[8];
    #pragma unroll
    for (int i = 0; i < 8; ++i) {
        float dv = dloc[i];
        dv += __shfl_xor_sync(0xffffffffu, dv, 1);
        dv += __shfl_xor_sync(0xffffffffu, dv, 2);
        dv += __shfl_xor_sync(0xffffffffu, dv, 4);
        dv += __shfl_xor_sync(0xffffffffu, dv, 8);
        inv[i] = 1.0f / (dv + padadd);
    }

    __syncthreads();   // all GEMM2 reads of Pp/Vs done; KsT free

    // agg (normalized) -> aggN natural [r][d]; Wo -> Wos.
    #pragma unroll
    for (int i = 0; i < 8; ++i) {
        u64 fd; PKDUP(fd, inv[i]);
        u64 t0 = Op[i][0], t1 = Op[i][1];
        asm("mul.rn.f32x2 %0, %0, %1;" : "+l"(t0) : "l"(fd));
        asm("mul.rn.f32x2 %0, %0, %1;" : "+l"(t1) : "l"(fd));
        float a0,a1,a2,a3;
        UNPK(a0, a1, t0);
        UNPK(a2, a3, t1);
        *reinterpret_cast<float4*>(&aggN[(rbase+i)*64 + (tx<<2)]) =
            make_float4(a0, a1, a2, a3);
    }
    {
        const float4* Wg = reinterpret_cast<const float4*>(Wo);
        #pragma unroll
        for (int q = 0; q < 16; ++q) {
            int idx4 = tid + q * 128;   // 0..2047
            reinterpret_cast<float4*>(Wos)[idx4] = Wg[idx4];
        }
    }
    __syncthreads();

    // ---- epilogue: out = relu([Q | agg] @ Wo + bo), 8 rows x 4 d ----
    u64 ec[8][2];
    #pragma unroll
    for (int i = 0; i < 8; ++i) { ec[i][0] = 0ull; ec[i][1] = 0ull; }

    #pragma unroll 4
    for (int c = 0; c < 64; ++c) {
        float4 a0 = *reinterpret_cast<const float4*>(&Qst[c*64 + rbase]);
        float4 a1 = *reinterpret_cast<const float4*>(&Qst[c*64 + rbase + 4]);
        ulonglong2 wb = *reinterpret_cast<const ulonglong2*>(&Wos[c*64 + (tx<<2)]);
        float av[8] = {a0.x, a0.y, a0.z, a0.w, a1.x, a1.y, a1.z, a1.w};
        #pragma unroll
        for (int i = 0; i < 8; ++i) {
            u64 ad; PKDUP(ad, av[i]);
            FMA2(ec[i][0], ad, wb.x);
            FMA2(ec[i][1], ad, wb.y);
        }
    }
    #pragma unroll 2
    for (int c0 = 0; c0 < 64; c0 += 4) {
        float ar[8][4];
        #pragma unroll
        for (int i = 0; i < 8; ++i) {
            float4 v = *reinterpret_cast<const float4*>(&aggN[(rbase+i)*64 + c0]);
            ar[i][0] = v.x; ar[i][1] = v.y; ar[i][2] = v.z; ar[i][3] = v.w;
        }
        #pragma unroll
        for (int cc = 0; cc < 4; ++cc) {
            ulonglong2 wb = *reinterpret_cast<const ulonglong2*>(&Wos[(64+c0+cc)*64 + (tx<<2)]);
            #pragma unroll
            for (int i = 0; i < 8; ++i) {
                u64 ad; PKDUP(ad, ar[i][cc]);
                FMA2(ec[i][0], ad, wb.x);
                FMA2(ec[i][1], ad, wb.y);
            }
        }
    }

    float bo4[4];
    #pragma unroll
    for (int j = 0; j < 4; ++j) bo4[j] = bo[(tx<<2) + j];

    #pragma unroll
    for (int i = 0; i < 8; ++i) {
        float e0,e1,e2,e3;
        UNPK(e0, e1, ec[i][0]);
        UNPK(e2, e3, ec[i][1]);
        size_t row = (size_t)bt * Ndim + half*64 + rbase + i;
        float4 o;
        o.x = fmaxf(e0 + bo4[0], 0.0f);
        o.y = fmaxf(e1 + bo4[1], 0.0f);
        o.z = fmaxf(e2 + bo4[2], 0.0f);
        o.w = fmaxf(e3 + bo4[3], 0.0f);
        *reinterpret_cast<float4*>(&out[row * Ddim + (tx<<2)]) = o;
    }
}

// ---------------------------------------------------------------------------
extern "C" void kernel_launch(void* const* d_in, const int* in_sizes, int n_in,
                              void* d_out, int out_size)
{
    const float* X  = (const float*)d_in[0];
    const float* Wq = (const float*)d_in[1];
    const float* bq = (const float*)d_in[2];
    const float* Wk = (const float*)d_in[3];
    const float* bk = (const float*)d_in[4];
    const float* Wv = (const float*)d_in[5];
    const float* bv = (const float*)d_in[6];
    const float* Wo = (const float*)d_in[7];
    const float* bo = (const float*)d_in[8];
    float* out = (float*)d_out;

    cudaFuncSetAttribute(attn_kernel,
                         cudaFuncAttributeMaxDynamicSharedMemorySize, SMEM_ATTN);

    qkv_kernel<<<dim3(ROWS/64, 3, 1), 256>>>(X, Wq, bq, Wk, bk, Wv, bv);
    attn_kernel<<<Bdim*Tdim*2, 128, SMEM_ATTN>>>(Wo, bo, out);
}

// round 8
// speedup vs baseline: 1.6715x; 1.1051x over previous
#include <cuda_runtime.h>
#include <cstdint>

// Problem constants
#define Bdim 8
#define Tdim 64
#define Ndim 128
#define Ddim 64
#define LAGn 8
#define ROWS (Bdim*Tdim*Ndim)   // 65536

typedef unsigned long long u64;

// Scratch (no cudaMalloc allowed)
// g_Q: [bt][f=64][n=128]  (TRANSPOSED)
// g_K: [bt][f=64][m=128]  (TRANSPOSED, pre-scaled by 0.125*log2(e))
// g_V: [bt][m=128][d=64]  (natural)
__device__ float g_Q[ROWS*Ddim];
__device__ float g_K[ROWS*Ddim];
__device__ float g_V[ROWS*Ddim];

// Packed fp32x2 helpers (sm_103a FFMA2 path — ptxas never auto-fuses these)
#define PKDUP(dst, f32v) asm("mov.b64 %0, {%1, %1};" : "=l"(dst) : "f"(f32v))
#define FMA2(acc, a, b)  asm("fma.rn.f32x2 %0, %1, %2, %0;" : "+l"(acc) : "l"(a), "l"(b))
#define UNPK(lo, hi, v)  asm("mov.b64 {%0, %1}, %2;" : "=f"(lo), "=f"(hi) : "l"(v))
#define EX2(y, x)        asm("ex2.approx.f32 %0, %1;" : "=f"(y) : "f"(x))

// cp.async helpers
#define CPA16(d, s)   asm volatile("cp.async.cg.shared.global [%0], [%1], 16;" :: "r"(d), "l"(s) : "memory")
#define CPA_COMMIT()  asm volatile("cp.async.commit_group;" ::: "memory")
#define CPA_WAIT0()   asm volatile("cp.async.wait_group 0;" ::: "memory")
#define CPA_WAIT1()   asm volatile("cp.async.wait_group 1;" ::: "memory")

__device__ __forceinline__ uint32_t smem_u32(const void* p) {
    uint32_t a;
    asm("{ .reg .u64 t; cvta.to.shared.u64 t, %1; cvt.u32.u64 %0, t; }" : "=r"(a) : "l"(p));
    return a;
}

// ---------------------------------------------------------------------------
// Kernel 1: QKV projection. grid = (512, 3). blockIdx.y: 0=Q,1=K,2=V.
// 256 threads, full 128-row (= one bt) tile per CTA.
// X staged transposed in smem with a 4-float-block XOR swizzle:
//   logical (f, r) lives at  XsT[f*128 + ((r>>2 ^ (f>>2 & 7))<<2) + (r&3)]
// -> conflict-free float4 stores (register 4x4 transpose) AND float4 loads.
// ---------------------------------------------------------------------------
__global__ __launch_bounds__(256) void qkv_kernel(
    const float* __restrict__ X,
    const float* __restrict__ Wq, const float* __restrict__ bq,
    const float* __restrict__ Wk, const float* __restrict__ bk,
    const float* __restrict__ Wv, const float* __restrict__ bv)
{
    __shared__ float XsT[64*128];   // 32 KB
    __shared__ float Ws [64*64];    // 16 KB
    __shared__ float bs [64];

    const float* W; const float* bias; float scale;
    if (blockIdx.y == 0)      { W = Wq; bias = bq; scale = 1.0f; }
    else if (blockIdx.y == 1) { W = Wk; bias = bk; scale = 0.125f * 1.4426950408889634f; }
    else                      { W = Wv; bias = bv; scale = 1.0f; }

    const int bt  = blockIdx.x;
    const int r0  = bt * 128;
    const int tid = threadIdx.x;

    {
        const float4* Xg = reinterpret_cast<const float4*>(X + (size_t)r0 * 64);
        const float4* Wg = reinterpret_cast<const float4*>(W);
        #pragma unroll
        for (int q = 0; q < 4; ++q) {
            int idx4 = tid + q * 256;     // 0..1023
            reinterpret_cast<float4*>(Ws)[idx4] = Wg[idx4];
        }
        #pragma unroll
        for (int b = 0; b < 2; ++b) {
            int blk = tid + b * 256;       // 0..511
            int r4  = blk >> 4;            // 0..31
            int f4  = blk & 15;            // 0..15
            float4 v0 = Xg[(r4*4+0)*16 + f4];
            float4 v1 = Xg[(r4*4+1)*16 + f4];
            float4 v2 = Xg[(r4*4+2)*16 + f4];
            float4 v3 = Xg[(r4*4+3)*16 + f4];
            int rb = (r4 ^ (f4 & 7)) << 2;
            *reinterpret_cast<float4*>(&XsT[(f4*4+0)*128 + rb]) = make_float4(v0.x, v1.x, v2.x, v3.x);
            *reinterpret_cast<float4*>(&XsT[(f4*4+1)*128 + rb]) = make_float4(v0.y, v1.y, v2.y, v3.y);
            *reinterpret_cast<float4*>(&XsT[(f4*4+2)*128 + rb]) = make_float4(v0.z, v1.z, v2.z, v3.z);
            *reinterpret_cast<float4*>(&XsT[(f4*4+3)*128 + rb]) = make_float4(v0.w, v1.w, v2.w, v3.w);
        }
        if (tid < 64) bs[tid] = bias[tid];
    }
    __syncthreads();

    const int tx = tid & 15;
    const int ty = tid >> 4;        // 0..15, 8 rows each
    const int rbase = ty << 3;

    u64 acc[8][2];
    #pragma unroll
    for (int i = 0; i < 8; ++i) { acc[i][0] = 0ull; acc[i][1] = 0ull; }

    #pragma unroll 4
    for (int k = 0; k < 64; ++k) {
        int sw = (k >> 2) & 7;
        float4 a0 = *reinterpret_cast<const float4*>(&XsT[k*128 + (((2*ty    ) ^ sw) << 2)]);
        float4 a1 = *reinterpret_cast<const float4*>(&XsT[k*128 + (((2*ty + 1) ^ sw) << 2)]);
        ulonglong2 b = *reinterpret_cast<const ulonglong2*>(&Ws[k*64 + (tx<<2)]);
        float av[8] = {a0.x, a0.y, a0.z, a0.w, a1.x, a1.y, a1.z, a1.w};
        #pragma unroll
        for (int i = 0; i < 8; ++i) {
            u64 ad; PKDUP(ad, av[i]);
            FMA2(acc[i][0], ad, b.x);
            FMA2(acc[i][1], ad, b.y);
        }
    }

    float o[8][4];
    #pragma unroll
    for (int i = 0; i < 8; ++i) {
        UNPK(o[i][0], o[i][1], acc[i][0]);
        UNPK(o[i][2], o[i][3], acc[i][1]);
        #pragma unroll
        for (int j = 0; j < 4; ++j)
            o[i][j] = fmaxf(o[i][j] + bs[(tx<<2)+j], 0.0f) * scale;
    }

    if (blockIdx.y == 2) {
        // V natural: [r][d]
        #pragma unroll
        for (int i = 0; i < 8; ++i) {
            int r = r0 + rbase + i;
            *reinterpret_cast<float4*>(&g_V[(size_t)r*64 + (tx<<2)]) =
                make_float4(o[i][0], o[i][1], o[i][2], o[i][3]);
        }
    } else {
        // Q/K transposed: [bt][d][n], float4 along n
        float* outp = blockIdx.y ? g_K : g_Q;
        #pragma unroll
        for (int j = 0; j < 4; ++j) {
            int d = (tx<<2) + j;
            float* base = &outp[(size_t)bt*8192 + d*128 + rbase];
            *reinterpret_cast<float4*>(base)     = make_float4(o[0][j], o[1][j], o[2][j], o[3][j]);
            *reinterpret_cast<float4*>(base + 4) = make_float4(o[4][j], o[5][j], o[6][j], o[7][j]);
        }
    }
}

// ---------------------------------------------------------------------------
// Kernel 2: fused lag-attention + output projection.
// grid = B*T*2 (each CTA: one (b,t), 64 of the 128 query heads), 128 threads.
// cp.async-pipelined K/V: K(l+1) issued after GEMM1(l), V(l+1) after GEMM2(l).
// Group discipline: every slot commits a (possibly empty) group, so
//   loop top: pending {K(l), V(l)} -> wait_group 1 releases K(l)
//   pre-GEMM2: pending {V(l), K(l+1)} -> wait_group 1 releases V(l)
// ---------------------------------------------------------------------------
#define SM_Q 0
#define SM_K 4096
#define SM_V 12288
#define SM_P 20480
#define SMEM_ATTN ((20480 + 8192)*4)   // 112 KB -> 2 CTAs/SM

__global__ __launch_bounds__(128, 2) void attn_kernel(
    const float* __restrict__ Wo, const float* __restrict__ bo,
    float* __restrict__ out)
{
    extern __shared__ float sm[];
    float* Qst = sm + SM_Q;     // [64 f][64 r]
    float* KsT = sm + SM_K;     // [64 f][128 m]
    float* Vs  = sm + SM_V;     // [128 m][64 d]
    float* Pp  = sm + SM_P;     // paired layout, 32 slots x 256 floats = 32 KB
    float* aggN = sm + SM_P;    // alias after loop: [64 r][64 d]
    float* Wos  = sm + SM_K;    // alias after loop: [128 c][64 d]

    const int gid  = blockIdx.x;
    const int half = gid & 1;
    const int bt   = gid >> 1;
    const int t    = bt & (Tdim - 1);
    const int tid  = threadIdx.x;
    const int tx   = tid & 15;
    const int ty   = tid >> 4;          // 0..7, 8 rows each
    const int w    = ty >> 1;
    const int p    = ty & 1;
    const int rbase = ty << 3;

    const uint32_t sQ = smem_u32(Qst);
    const uint32_t sK = smem_u32(KsT);
    const uint32_t sV = smem_u32(Vs);

    // Prologue: Q tile + first K/V chunk via cp.async (group 0).
    {
        const float4* Qg = reinterpret_cast<const float4*>(g_Q + (size_t)bt*8192) + half*16;
        const float4* Kg = reinterpret_cast<const float4*>(g_K + (size_t)bt*8192);
        const float4* Vg = reinterpret_cast<const float4*>(g_V + (size_t)bt*8192);
        #pragma unroll
        for (int q = 0; q < 8; ++q) {
            int idx4 = tid + q * 128;        // 0..1023
            CPA16(sQ + (uint32_t)idx4*16, Qg + (idx4 >> 4)*32 + (idx4 & 15));
        }
        #pragma unroll
        for (int q = 0; q < 16; ++q) {
            int idx4 = tid + q * 128;        // 0..2047
            CPA16(sK + (uint32_t)idx4*16, Kg + idx4);
            CPA16(sV + (uint32_t)idx4*16, Vg + idx4);
        }
        CPA_COMMIT();
    }

    float dloc[8];
    u64 Op[8][2];
    #pragma unroll
    for (int i = 0; i < 8; ++i) { dloc[i] = 0.0f; Op[i][0] = 0ull; Op[i][1] = 0ull; }

    const int nvalid = (t + 1 < LAGn) ? (t + 1) : LAGn;

    for (int l = 0; l < nvalid; ++l) {
        if (l == 0) { CPA_WAIT0(); } else { CPA_WAIT1(); }
        __syncthreads();   // K(l) visible everywhere; Pp free (prev GEMM2 done)

        // ---- GEMM1: S = Q·K^T, 8 rows x (cols tx*4..+3, 64+tx*4..+3) ----
        u64 sa[8][4];
        #pragma unroll
        for (int i = 0; i < 8; ++i)
            #pragma unroll
            for (int j = 0; j < 4; ++j) sa[i][j] = 0ull;

        #pragma unroll 4
        for (int k = 0; k < 64; ++k) {
            float4 a0 = *reinterpret_cast<const float4*>(&Qst[k*64 + rbase]);
            float4 a1 = *reinterpret_cast<const float4*>(&Qst[k*64 + rbase + 4]);
            ulonglong2 b0 = *reinterpret_cast<const ulonglong2*>(&KsT[k*128 + (tx<<2)]);
            ulonglong2 b1 = *reinterpret_cast<const ulonglong2*>(&KsT[k*128 + 64 + (tx<<2)]);
            float av[8] = {a0.x, a0.y, a0.z, a0.w, a1.x, a1.y, a1.z, a1.w};
            #pragma unroll
            for (int i = 0; i < 8; ++i) {
                u64 ad; PKDUP(ad, av[i]);
                FMA2(sa[i][0], ad, b0.x);
                FMA2(sa[i][1], ad, b0.y);
                FMA2(sa[i][2], ad, b1.x);
                FMA2(sa[i][3], ad, b1.y);
            }
        }

        // ---- 2^s (log2e folded into K) + denom partials + paired P store ----
        #pragma unroll
        for (int i = 0; i < 8; ++i) {
            float e[8];
            UNPK(e[0], e[1], sa[i][0]);
            UNPK(e[2], e[3], sa[i][1]);
            UNPK(e[4], e[5], sa[i][2]);
            UNPK(e[6], e[7], sa[i][3]);
            float rs = 0.0f;
            #pragma unroll
            for (int j = 0; j < 8; ++j) { float pe; EX2(pe, e[j]); e[j] = pe; rs += pe; }
            dloc[i] += rs;
            float* base = &Pp[(((i<<2) + w) << 8) + (p<<2)];
            *reinterpret_cast<float4*>(base + (tx<<3)) =
                make_float4(e[0], e[1], e[2], e[3]);
            *reinterpret_cast<float4*>(base + ((16 + tx)<<3)) =
                make_float4(e[4], e[5], e[6], e[7]);
        }
        __syncthreads();   // Pp visible; all GEMM1 reads of KsT done

        // Prefetch K(l+1) into the just-freed K buffer (overlaps GEMM2).
        if (l + 1 < nvalid) {
            const float4* Kg = reinterpret_cast<const float4*>(g_K + (size_t)(bt - l - 1) * 8192);
            #pragma unroll
            for (int q = 0; q < 16; ++q) {
                int idx4 = tid + q * 128;
                CPA16(sK + (uint32_t)idx4*16, Kg + idx4);
            }
        }
        CPA_COMMIT();
        CPA_WAIT1();       // V(l) done (older than the K group just committed)
        __syncthreads();

        // ---- GEMM2: O += P @ V, 8 rows x 4 d-cols (d = tx*4..+3) ----
        #pragma unroll 2
        for (int m0 = 0; m0 < 128; m0 += 4) {
            float ar[8][4];
            #pragma unroll
            for (int i = 0; i < 8; ++i) {
                float4 v = *reinterpret_cast<const float4*>(
                    &Pp[(((i<<2) + w) << 8) + ((m0 >> 2)<<3) + (p<<2)]);
                ar[i][0] = v.x; ar[i][1] = v.y; ar[i][2] = v.z; ar[i][3] = v.w;
            }
            #pragma unroll
            for (int mm = 0; mm < 4; ++mm) {
                ulonglong2 vb = *reinterpret_cast<const ulonglong2*>(&Vs[(m0+mm)*64 + (tx<<2)]);
                #pragma unroll
                for (int i = 0; i < 8; ++i) {
                    u64 pd; PKDUP(pd, ar[i][mm]);
                    FMA2(Op[i][0], pd, vb.x);
                    FMA2(Op[i][1], pd, vb.y);
                }
            }
        }
        __syncthreads();   // all GEMM2 reads of Vs done

        // Prefetch V(l+1) (overlaps next GEMM1).
        if (l + 1 < nvalid) {
            const float4* Vg = reinterpret_cast<const float4*>(g_V + (size_t)(bt - l - 1) * 8192);
            #pragma unroll
            for (int q = 0; q < 16; ++q) {
                int idx4 = tid + q * 128;
                CPA16(sV + (uint32_t)idx4*16, Vg + idx4);
            }
        }
        CPA_COMMIT();
    }

    // ---- finalize denominators (reduce over the 16 tx lanes, once) ----
    const float padadd = (float)(LAGn - nvalid) * 128.0f;   // 2^0 per padded key
    float inv[8];
    #pragma unroll
    for (int i = 0; i < 8; ++i) {
        float dv = dloc[i];
        dv += __shfl_xor_sync(0xffffffffu, dv, 1);
        dv += __shfl_xor_sync(0xffffffffu, dv, 2);
        dv += __shfl_xor_sync(0xffffffffu, dv, 4);
        dv += __shfl_xor_sync(0xffffffffu, dv, 8);
        inv[i] = 1.0f / (dv + padadd);
    }

    CPA_WAIT0();
    __syncthreads();   // drain pipeline; KsT/Pp reusable

    // agg (normalized) -> aggN natural [r][d]; Wo -> Wos.
    #pragma unroll
    for (int i = 0; i < 8; ++i) {
        u64 fd; PKDUP(fd, inv[i]);
        u64 t0 = Op[i][0], t1 = Op[i][1];
        asm("mul.rn.f32x2 %0, %0, %1;" : "+l"(t0) : "l"(fd));
        asm("mul.rn.f32x2 %0, %0, %1;" : "+l"(t1) : "l"(fd));
        float a0,a1,a2,a3;
        UNPK(a0, a1, t0);
        UNPK(a2, a3, t1);
        *reinterpret_cast<float4*>(&aggN[(rbase+i)*64 + (tx<<2)]) =
            make_float4(a0, a1, a2, a3);
    }
    {
        const float4* Wg = reinterpret_cast<const float4*>(Wo);
        #pragma unroll
        for (int q = 0; q < 16; ++q) {
            int idx4 = tid + q * 128;   // 0..2047
            reinterpret_cast<float4*>(Wos)[idx4] = Wg[idx4];
        }
    }
    __syncthreads();

    // ---- epilogue: out = relu([Q | agg] @ Wo + bo), 8 rows x 4 d ----
    u64 ec[8][2];
    #pragma unroll
    for (int i = 0; i < 8; ++i) { ec[i][0] = 0ull; ec[i][1] = 0ull; }

    #pragma unroll 4
    for (int c = 0; c < 64; ++c) {
        float4 a0 = *reinterpret_cast<const float4*>(&Qst[c*64 + rbase]);
        float4 a1 = *reinterpret_cast<const float4*>(&Qst[c*64 + rbase + 4]);
        ulonglong2 wb = *reinterpret_cast<const ulonglong2*>(&Wos[c*64 + (tx<<2)]);
        float av[8] = {a0.x, a0.y, a0.z, a0.w, a1.x, a1.y, a1.z, a1.w};
        #pragma unroll
        for (int i = 0; i < 8; ++i) {
            u64 ad; PKDUP(ad, av[i]);
            FMA2(ec[i][0], ad, wb.x);
            FMA2(ec[i][1], ad, wb.y);
        }
    }
    #pragma unroll 2
    for (int c0 = 0; c0 < 64; c0 += 4) {
        float ar[8][4];
        #pragma unroll
        for (int i = 0; i < 8; ++i) {
            float4 v = *reinterpret_cast<const float4*>(&aggN[(rbase+i)*64 + c0]);
            ar[i][0] = v.x; ar[i][1] = v.y; ar[i][2] = v.z; ar[i][3] = v.w;
        }
        #pragma unroll
        for (int cc = 0; cc < 4; ++cc) {
            ulonglong2 wb = *reinterpret_cast<const ulonglong2*>(&Wos[(64+c0+cc)*64 + (tx<<2)]);
            #pragma unroll
            for (int i = 0; i < 8; ++i) {
                u64 ad; PKDUP(ad, ar[i][cc]);
                FMA2(ec[i][0], ad, wb.x);
                FMA2(ec[i][1], ad, wb.y);
            }
        }
    }

    float bo4[4];
    #pragma unroll
    for (int j = 0; j < 4; ++j) bo4[j] = bo[(tx<<2) + j];

    #pragma unroll
    for (int i = 0; i < 8; ++i) {
        float e0,e1,e2,e3;
        UNPK(e0, e1, ec[i][0]);
        UNPK(e2, e3, ec[i][1]);
        size_t row = (size_t)bt * Ndim + half*64 + rbase + i;
        float4 o;
        o.x = fmaxf(e0 + bo4[0], 0.0f);
        o.y = fmaxf(e1 + bo4[1], 0.0f);
        o.z = fmaxf(e2 + bo4[2], 0.0f);
        o.w = fmaxf(e3 + bo4[3], 0.0f);
        *reinterpret_cast<float4*>(&out[row * Ddim + (tx<<2)]) = o;
    }
}

// ---------------------------------------------------------------------------
extern "C" void kernel_launch(void* const* d_in, const int* in_sizes, int n_in,
                              void* d_out, int out_size)
{
    const float* X  = (const float*)d_in[0];
    const float* Wq = (const float*)d_in[1];
    const float* bq = (const float*)d_in[2];
    const float* Wk = (const float*)d_in[3];
    const float* bk = (const float*)d_in[4];
    const float* Wv = (const float*)d_in[5];
    const float* bv = (const float*)d_in[6];
    const float* Wo = (const float*)d_in[7];
    const float* bo = (const float*)d_in[8];
    float* out = (float*)d_out;

    cudaFuncSetAttribute(attn_kernel,
                         cudaFuncAttributeMaxDynamicSharedMemorySize, SMEM_ATTN);

    qkv_kernel<<<dim3(Bdim*Tdim, 3, 1), 256>>>(X, Wq, bq, Wk, bk, Wv, bv);
    attn_kernel<<<Bdim*Tdim*2, 128, SMEM_ATTN>>>(Wo, bo, out);
}

// round 9
// speedup vs baseline: 1.7234x; 1.0310x over previous
#include <cuda_runtime.h>
#include <cstdint>

// Problem constants
#define Bdim 8
#define Tdim 64
#define Ndim 128
#define Ddim 64
#define LAGn 8
#define ROWS (Bdim*Tdim*Ndim)   // 65536

typedef unsigned long long u64;

// Scratch (no cudaMalloc allowed)
// g_Q: [bt][f=64][n=128]  (TRANSPOSED)
// g_K: [bt][f=64][m=128]  (TRANSPOSED, pre-scaled by 0.125*log2(e))
// g_V: [bt][m=128][d=64]  (natural)
__device__ float g_Q[ROWS*Ddim];
__device__ float g_K[ROWS*Ddim];
__device__ float g_V[ROWS*Ddim];

// Packed fp32x2 helpers
#define PKDUP(dst, f32v) asm("mov.b64 %0, {%1, %1};" : "=l"(dst) : "f"(f32v))
#define PK2(dst, lo, hi) asm("mov.b64 %0, {%1, %2};" : "=l"(dst) : "f"(lo), "f"(hi))
#define FMA2(acc, a, b)  asm("fma.rn.f32x2 %0, %1, %2, %0;" : "+l"(acc) : "l"(a), "l"(b))
#define MUL2(acc, a)     asm("mul.rn.f32x2 %0, %0, %1;" : "+l"(acc) : "l"(a))
#define UNPK(lo, hi, v)  asm("mov.b64 {%0, %1}, %2;" : "=f"(lo), "=f"(hi) : "l"(v))
#define EX2(y, x)        asm("ex2.approx.f32 %0, %1;" : "=f"(y) : "f"(x))

// cp.async helpers
#define CPA16(d, s)   asm volatile("cp.async.cg.shared.global [%0], [%1], 16;" :: "r"(d), "l"(s) : "memory")
#define CPA_COMMIT()  asm volatile("cp.async.commit_group;" ::: "memory")
#define CPA_WAIT0()   asm volatile("cp.async.wait_group 0;" ::: "memory")
#define CPA_WAIT1()   asm volatile("cp.async.wait_group 1;" ::: "memory")

__device__ __forceinline__ uint32_t smem_u32(const void* p) {
    uint32_t a;
    asm("{ .reg .u64 t; cvta.to.shared.u64 t, %1; cvt.u32.u64 %0, t; }" : "=r"(a) : "l"(p));
    return a;
}

// ---------------------------------------------------------------------------
// Kernel 1: QKV projection (unchanged from R8). grid = (512, 3).
// ---------------------------------------------------------------------------
__global__ __launch_bounds__(256) void qkv_kernel(
    const float* __restrict__ X,
    const float* __restrict__ Wq, const float* __restrict__ bq,
    const float* __restrict__ Wk, const float* __restrict__ bk,
    const float* __restrict__ Wv, const float* __restrict__ bv)
{
    __shared__ float XsT[64*128];   // 32 KB
    __shared__ float Ws [64*64];    // 16 KB
    __shared__ float bs [64];

    const float* W; const float* bias; float scale;
    if (blockIdx.y == 0)      { W = Wq; bias = bq; scale = 1.0f; }
    else if (blockIdx.y == 1) { W = Wk; bias = bk; scale = 0.125f * 1.4426950408889634f; }
    else                      { W = Wv; bias = bv; scale = 1.0f; }

    const int bt  = blockIdx.x;
    const int r0  = bt * 128;
    const int tid = threadIdx.x;

    {
        const float4* Xg = reinterpret_cast<const float4*>(X + (size_t)r0 * 64);
        const float4* Wg = reinterpret_cast<const float4*>(W);
        #pragma unroll
        for (int q = 0; q < 4; ++q) {
            int idx4 = tid + q * 256;
            reinterpret_cast<float4*>(Ws)[idx4] = Wg[idx4];
        }
        #pragma unroll
        for (int b = 0; b < 2; ++b) {
            int blk = tid + b * 256;
            int r4  = blk >> 4;
            int f4  = blk & 15;
            float4 v0 = Xg[(r4*4+0)*16 + f4];
            float4 v1 = Xg[(r4*4+1)*16 + f4];
            float4 v2 = Xg[(r4*4+2)*16 + f4];
            float4 v3 = Xg[(r4*4+3)*16 + f4];
            int rb = (r4 ^ (f4 & 7)) << 2;
            *reinterpret_cast<float4*>(&XsT[(f4*4+0)*128 + rb]) = make_float4(v0.x, v1.x, v2.x, v3.x);
            *reinterpret_cast<float4*>(&XsT[(f4*4+1)*128 + rb]) = make_float4(v0.y, v1.y, v2.y, v3.y);
            *reinterpret_cast<float4*>(&XsT[(f4*4+2)*128 + rb]) = make_float4(v0.z, v1.z, v2.z, v3.z);
            *reinterpret_cast<float4*>(&XsT[(f4*4+3)*128 + rb]) = make_float4(v0.w, v1.w, v2.w, v3.w);
        }
        if (tid < 64) bs[tid] = bias[tid];
    }
    __syncthreads();

    const int tx = tid & 15;
    const int ty = tid >> 4;
    const int rbase = ty << 3;

    u64 acc[8][2];
    #pragma unroll
    for (int i = 0; i < 8; ++i) { acc[i][0] = 0ull; acc[i][1] = 0ull; }

    #pragma unroll 4
    for (int k = 0; k < 64; ++k) {
        int sw = (k >> 2) & 7;
        float4 a0 = *reinterpret_cast<const float4*>(&XsT[k*128 + (((2*ty    ) ^ sw) << 2)]);
        float4 a1 = *reinterpret_cast<const float4*>(&XsT[k*128 + (((2*ty + 1) ^ sw) << 2)]);
        ulonglong2 b = *reinterpret_cast<const ulonglong2*>(&Ws[k*64 + (tx<<2)]);
        float av[8] = {a0.x, a0.y, a0.z, a0.w, a1.x, a1.y, a1.z, a1.w};
        #pragma unroll
        for (int i = 0; i < 8; ++i) {
            u64 ad; PKDUP(ad, av[i]);
            FMA2(acc[i][0], ad, b.x);
            FMA2(acc[i][1], ad, b.y);
        }
    }

    float o[8][4];
    #pragma unroll
    for (int i = 0; i < 8; ++i) {
        UNPK(o[i][0], o[i][1], acc[i][0]);
        UNPK(o[i][2], o[i][3], acc[i][1]);
        #pragma unroll
        for (int j = 0; j < 4; ++j)
            o[i][j] = fmaxf(o[i][j] + bs[(tx<<2)+j], 0.0f) * scale;
    }

    if (blockIdx.y == 2) {
        #pragma unroll
        for (int i = 0; i < 8; ++i) {
            int r = r0 + rbase + i;
            *reinterpret_cast<float4*>(&g_V[(size_t)r*64 + (tx<<2)]) =
                make_float4(o[i][0], o[i][1], o[i][2], o[i][3]);
        }
    } else {
        float* outp = blockIdx.y ? g_K : g_Q;
        #pragma unroll
        for (int j = 0; j < 4; ++j) {
            int d = (tx<<2) + j;
            float* base = &outp[(size_t)bt*8192 + d*128 + rbase];
            *reinterpret_cast<float4*>(base)     = make_float4(o[0][j], o[1][j], o[2][j], o[3][j]);
            *reinterpret_cast<float4*>(base + 4) = make_float4(o[4][j], o[5][j], o[6][j], o[7][j]);
        }
    }
}

// ---------------------------------------------------------------------------
// Kernel 2: fused lag-attention + output projection.
// grid = B*T*2, 128 threads, 64 KB smem -> 3 CTAs/SM.
// 64-key chunks (2 per lag). Row-pair packed FFMA2 everywhere.
// P layout: [m][rp-unit swizzled]; unit16B U = (rp>>1) ^ ((m>>2)&7),
//   u64 offset within unit = rp&1. Writer key (tx&7) == reader key ((m>>2)&7).
// aggT layout: [c][rp ^ (((c>>2)&7)<<1)] u64 pairs (bit0 preserved).
// ---------------------------------------------------------------------------
#define SM_Q 0
#define SM_K 4096
#define SM_V 8192
#define SM_P 12288
#define SMEM_ATTN (16384*4)   // 64 KB

__global__ __launch_bounds__(128, 3) void attn_kernel(
    const float* __restrict__ Wo, const float* __restrict__ bo,
    float* __restrict__ out)
{
    extern __shared__ float sm[];
    float* Qst = sm + SM_Q;     // [64 f][64 r]
    float* KsT = sm + SM_K;     // [64 f][64 m]   (current 64-key chunk)
    float* Vs  = sm + SM_V;     // [64 m][64 d]
    float* Pp  = sm + SM_P;     // [64 m][32 rp u64, swizzled] 16 KB
    float* aggT = sm + SM_P;    // alias: [64 c][32 rp u64, swizzled]
    float* Wos  = sm + SM_K;    // alias: [128 c][64 d] = 32 KB (K+V regions)

    const int gid  = blockIdx.x;
    const int half = gid & 1;
    const int bt   = gid >> 1;
    const int t    = bt & (Tdim - 1);
    const int tid  = threadIdx.x;
    const int tx   = tid & 15;
    const int ty   = tid >> 4;          // 0..7
    const int rbase = ty << 3;
    const int xsw  = tx & 7;            // P swizzle key for this thread's m's

    const uint32_t sQ = smem_u32(Qst);
    const uint32_t sK = smem_u32(KsT);
    const uint32_t sV = smem_u32(Vs);

    // Prologue: Q tile + first K/V chunk (c=0) via cp.async (group 0).
    {
        const float4* Qg = reinterpret_cast<const float4*>(g_Q + (size_t)bt*8192) + half*16;
        const float*  Kg = g_K + (size_t)bt*8192;
        const float*  Vg = g_V + (size_t)bt*8192;
        #pragma unroll
        for (int q = 0; q < 8; ++q) {
            int idx4 = tid + q * 128;        // 0..1023
            CPA16(sQ + (uint32_t)idx4*16, Qg + (idx4 >> 4)*32 + (idx4 & 15));
        }
        #pragma unroll
        for (int q = 0; q < 8; ++q) {
            int idx4 = tid + q * 128;        // 0..1023
            int f = idx4 >> 4, u = idx4 & 15;
            CPA16(sK + (uint32_t)idx4*16, Kg + f*128 + u*4);
            CPA16(sV + (uint32_t)idx4*16, Vg + idx4*4);
        }
        CPA_COMMIT();
    }

    float dloc[8];
    u64 Op[4][4];   // [rp][d] : rows (rbase+2i, rbase+2i+1), d = tx*4+dd
    #pragma unroll
    for (int i = 0; i < 8; ++i) dloc[i] = 0.0f;
    #pragma unroll
    for (int i = 0; i < 4; ++i)
        #pragma unroll
        for (int d = 0; d < 4; ++d) Op[i][d] = 0ull;

    const int nvalid  = (t + 1 < LAGn) ? (t + 1) : LAGn;
    const int nchunks = nvalid * 2;

    for (int ic = 0; ic < nchunks; ++ic) {
        if (ic == 0) { CPA_WAIT0(); } else { CPA_WAIT1(); }
        __syncthreads();   // K(ic) visible; Pp free

        // ---- GEMM1: S = Q·K^T, row-pair packed: sa[rp 0..3][m 0..3] ----
        u64 sa[4][4];
        #pragma unroll
        for (int i = 0; i < 4; ++i)
            #pragma unroll
            for (int m = 0; m < 4; ++m) sa[i][m] = 0ull;

        #pragma unroll 4
        for (int k = 0; k < 64; ++k) {
            ulonglong2 a01 = *reinterpret_cast<const ulonglong2*>(&Qst[k*64 + rbase]);
            ulonglong2 a23 = *reinterpret_cast<const ulonglong2*>(&Qst[k*64 + rbase + 4]);
            float4 bv = *reinterpret_cast<const float4*>(&KsT[k*64 + (tx<<2)]);
            float bs4[4] = {bv.x, bv.y, bv.z, bv.w};
            #pragma unroll
            for (int m = 0; m < 4; ++m) {
                u64 bd; PKDUP(bd, bs4[m]);
                FMA2(sa[0][m], a01.x, bd);
                FMA2(sa[1][m], a01.y, bd);
                FMA2(sa[2][m], a23.x, bd);
                FMA2(sa[3][m], a23.y, bd);
            }
        }

        // ---- 2^s + denom partials + packed P store ----
        #pragma unroll
        for (int i = 0; i < 4; ++i) {
            const int rp = (ty<<2) + i;
            const int uoff = (((rp>>1) ^ xsw) << 2) + ((rp & 1) << 1);
            #pragma unroll
            for (int m = 0; m < 4; ++m) {
                float lo, hi;
                UNPK(lo, hi, sa[i][m]);
                float elo, ehi;
                EX2(elo, lo); EX2(ehi, hi);
                dloc[2*i]   += elo;
                dloc[2*i+1] += ehi;
                u64 pe; PK2(pe, elo, ehi);
                *reinterpret_cast<u64*>(&Pp[((tx<<2)+m)*64 + uoff]) = pe;
            }
        }
        __syncthreads();   // Pp visible; GEMM1 done with KsT

        // Prefetch K(ic+1) (overlaps GEMM2).
        if (ic + 1 < nchunks) {
            const float* Kg = g_K + (size_t)(bt - ((ic+1)>>1)) * 8192 + ((ic+1)&1)*64;
            #pragma unroll
            for (int q = 0; q < 8; ++q) {
                int idx4 = tid + q * 128;
                int f = idx4 >> 4, u = idx4 & 15;
                CPA16(sK + (uint32_t)idx4*16, Kg + f*128 + u*4);
            }
        }
        CPA_COMMIT();
        CPA_WAIT1();       // V(ic) done
        __syncthreads();

        // ---- GEMM2: O += P @ V, row-pair packed ----
        #pragma unroll 2
        for (int m0 = 0; m0 < 64; m0 += 4) {
            const int x = (m0 >> 2) & 7;
            #pragma unroll
            for (int mm = 0; mm < 4; ++mm) {
                const int m = m0 + mm;
                ulonglong2 p01 = *reinterpret_cast<const ulonglong2*>(
                    &Pp[m*64 + ((((ty<<1)    ) ^ x) << 2)]);
                ulonglong2 p23 = *reinterpret_cast<const ulonglong2*>(
                    &Pp[m*64 + ((((ty<<1) + 1) ^ x) << 2)]);
                float4 vv = *reinterpret_cast<const float4*>(&Vs[m*64 + (tx<<2)]);
                float vs4[4] = {vv.x, vv.y, vv.z, vv.w};
                #pragma unroll
                for (int d = 0; d < 4; ++d) {
                    u64 vd; PKDUP(vd, vs4[d]);
                    FMA2(Op[0][d], p01.x, vd);
                    FMA2(Op[1][d], p01.y, vd);
                    FMA2(Op[2][d], p23.x, vd);
                    FMA2(Op[3][d], p23.y, vd);
                }
            }
        }
        __syncthreads();   // GEMM2 done with Vs

        // Prefetch V(ic+1) (overlaps next GEMM1).
        if (ic + 1 < nchunks) {
            const float* Vg = g_V + ((size_t)(bt - ((ic+1)>>1)) * 128 + ((ic+1)&1)*64) * 64;
            #pragma unroll
            for (int q = 0; q < 8; ++q) {
                int idx4 = tid + q * 128;
                CPA16(sV + (uint32_t)idx4*16, Vg + idx4*4);
            }
        }
        CPA_COMMIT();
    }

    // ---- denominators: reduce over 16 tx lanes, build packed inverses ----
    const float padadd = (float)(LAGn - nvalid) * 128.0f;   // 2^0 per padded key
    u64 invp[4];
    #pragma unroll
    for (int i = 0; i < 4; ++i) {
        float d0 = dloc[2*i], d1 = dloc[2*i+1];
        d0 += __shfl_xor_sync(0xffffffffu, d0, 1);
        d1 += __shfl_xor_sync(0xffffffffu, d1, 1);
        d0 += __shfl_xor_sync(0xffffffffu, d0, 2);
        d1 += __shfl_xor_sync(0xffffffffu, d1, 2);
        d0 += __shfl_xor_sync(0xffffffffu, d0, 4);
        d1 += __shfl_xor_sync(0xffffffffu, d1, 4);
        d0 += __shfl_xor_sync(0xffffffffu, d0, 8);
        d1 += __shfl_xor_sync(0xffffffffu, d1, 8);
        PK2(invp[i], 1.0f / (d0 + padadd), 1.0f / (d1 + padadd));
    }

    CPA_WAIT0();
    __syncthreads();   // drain; Pp/KsT/Vs reusable

    // agg (normalized, row-pair u64) -> aggT swizzled; Wo -> Wos.
    #pragma unroll
    for (int i = 0; i < 4; ++i) {
        const int rp = (ty<<2) + i;
        #pragma unroll
        for (int dd = 0; dd < 4; ++dd) {
            MUL2(Op[i][dd], invp[i]);
            const int c = (tx<<2) + dd;
            *reinterpret_cast<u64*>(&aggT[c*64 + ((rp ^ (xsw<<1)) << 1)]) = Op[i][dd];
        }
    }
    {
        const float4* Wg = reinterpret_cast<const float4*>(Wo);
        #pragma unroll
        for (int q = 0; q < 16; ++q) {
            int idx4 = tid + q * 128;   // 0..2047
            reinterpret_cast<float4*>(Wos)[idx4] = Wg[idx4];
        }
    }
    __syncthreads();

    // ---- epilogue: out = relu([Q | agg] @ Wo + bo), row-pair packed ----
    u64 ec[4][4];
    #pragma unroll
    for (int i = 0; i < 4; ++i)
        #pragma unroll
        for (int d = 0; d < 4; ++d) ec[i][d] = 0ull;

    #pragma unroll 4
    for (int c = 0; c < 64; ++c) {
        ulonglong2 a01 = *reinterpret_cast<const ulonglong2*>(&Qst[c*64 + rbase]);
        ulonglong2 a23 = *reinterpret_cast<const ulonglong2*>(&Qst[c*64 + rbase + 4]);
        float4 wv = *reinterpret_cast<const float4*>(&Wos[c*64 + (tx<<2)]);
        float ws4[4] = {wv.x, wv.y, wv.z, wv.w};
        #pragma unroll
        for (int d = 0; d < 4; ++d) {
            u64 wd; PKDUP(wd, ws4[d]);
            FMA2(ec[0][d], a01.x, wd);
            FMA2(ec[1][d], a01.y, wd);
            FMA2(ec[2][d], a23.x, wd);
            FMA2(ec[3][d], a23.y, wd);
        }
    }
    #pragma unroll 4
    for (int c = 0; c < 64; ++c) {
        const int y = ((c >> 2) & 7) << 1;
        ulonglong2 a01 = *reinterpret_cast<const ulonglong2*>(
            &aggT[c*64 + ((((ty<<2)    ) ^ y) << 1)]);
        ulonglong2 a23 = *reinterpret_cast<const ulonglong2*>(
            &aggT[c*64 + ((((ty<<2) + 2) ^ y) << 1)]);
        float4 wv = *reinterpret_cast<const float4*>(&Wos[(64+c)*64 + (tx<<2)]);
        float ws4[4] = {wv.x, wv.y, wv.z, wv.w};
        #pragma unroll
        for (int d = 0; d < 4; ++d) {
            u64 wd; PKDUP(wd, ws4[d]);
            FMA2(ec[0][d], a01.x, wd);
            FMA2(ec[1][d], a01.y, wd);
            FMA2(ec[2][d], a23.x, wd);
            FMA2(ec[3][d], a23.y, wd);
        }
    }

    float bo4[4];
    #pragma unroll
    for (int j = 0; j < 4; ++j) bo4[j] = bo[(tx<<2) + j];

    #pragma unroll
    for (int i = 0; i < 4; ++i) {
        float e0[4], e1[4];
        #pragma unroll
        for (int d = 0; d < 4; ++d) UNPK(e0[d], e1[d], ec[i][d]);
        size_t row0 = (size_t)bt * Ndim + half*64 + rbase + 2*i;
        float4 o0, o1;
        o0.x = fmaxf(e0[0] + bo4[0], 0.0f);
        o0.y = fmaxf(e0[1] + bo4[1], 0.0f);
        o0.z = fmaxf(e0[2] + bo4[2], 0.0f);
        o0.w = fmaxf(e0[3] + bo4[3], 0.0f);
        o1.x = fmaxf(e1[0] + bo4[0], 0.0f);
        o1.y = fmaxf(e1[1] + bo4[1], 0.0f);
        o1.z = fmaxf(e1[2] + bo4[2], 0.0f);
        o1.w = fmaxf(e1[3] + bo4[3], 0.0f);
        *reinterpret_cast<float4*>(&out[row0 * Ddim + (tx<<2)])       = o0;
        *reinterpret_cast<float4*>(&out[(row0 + 1) * Ddim + (tx<<2)]) = o1;
    }
}

// ---------------------------------------------------------------------------
extern "C" void kernel_launch(void* const* d_in, const int* in_sizes, int n_in,
                              void* d_out, int out_size)
{
    const float* X  = (const float*)d_in[0];
    const float* Wq = (const float*)d_in[1];
    const float* bq = (const float*)d_in[2];
    const float* Wk = (const float*)d_in[3];
    const float* bk = (const float*)d_in[4];
    const float* Wv = (const float*)d_in[5];
    const float* bv = (const float*)d_in[6];
    const float* Wo = (const float*)d_in[7];
    const float* bo = (const float*)d_in[8];
    float* out = (float*)d_out;

    cudaFuncSetAttribute(attn_kernel,
                         cudaFuncAttributeMaxDynamicSharedMemorySize, SMEM_ATTN);

    qkv_kernel<<<dim3(Bdim*Tdim, 3, 1), 256>>>(X, Wq, bq, Wk, bk, Wv, bv);
    attn_kernel<<<Bdim*Tdim*2, 128, SMEM_ATTN>>>(Wo, bo, out);
}